// round 17
// baseline (speedup 1.0000x reference)
#include <cuda_runtime.h>
#include <cuda_fp16.h>
#include <cstdint>

#define DD 256          // feature dim
#define NP 256          // points per group
#define MAXG 128        // groups
#define TPB 256
#define GRID_CTAS 296   // 2 per SM on 148-SM B300 (<= resident at occ 2)
#define PREP_CTAS 96    // producer CTAs

// ---------------------------------------------------------------------------
// Scratch (no cudaMalloc allowed)
// ---------------------------------------------------------------------------
__device__ __half g_xh[MAXG * NP * DD];
__device__ __half g_yh[MAXG * NP * DD];
__device__ float g_xn[MAXG * NP], g_yn[MAXG * NP];
__device__ float g_part[10 * MAXG];
__device__ unsigned int g_ready[MAXG];   // prep tasks done per group (target 256)
__device__ unsigned int g_cursor;        // GEMM work-item cursor
__device__ unsigned int g_done;          // finished-CTA counter

__device__ __forceinline__ uint32_t smem_u32(const void* p) {
    uint32_t a;
    asm("{ .reg .u64 t; cvta.to.shared.u64 t, %1; cvt.u32.u64 %0, t; }"
        : "=r"(a) : "l"(p));
    return a;
}
__device__ __forceinline__ unsigned int ld_acq(const unsigned int* p) {
    unsigned int v;
    asm volatile("ld.acquire.gpu.global.u32 %0, [%1];" : "=r"(v) : "l"(p));
    return v;
}

// warp tile offsets (2 warps in M, 4 in N) — defined BEFORE use
__device__ __forceinline__ int wm_of(int wid) { return (wid & 1) * 64; }
__device__ __forceinline__ int wn_of(int wid) { return (wid >> 1) * 32; }

#define CP_ASYNC16(so, gp) \
    asm volatile("cp.async.cg.shared.global [%0], [%1], 16;" :: "r"(so), "l"(gp))
#define CP_COMMIT() asm volatile("cp.async.commit_group;" ::: "memory")
#define CP_WAIT0()  asm volatile("cp.async.wait_group 0;" ::: "memory")

#define LDSM_X4(r0, r1, r2, r3, addr) \
    asm volatile("ldmatrix.sync.aligned.m8n8.x4.shared.b16 {%0,%1,%2,%3}, [%4];" \
                 : "=r"(r0), "=r"(r1), "=r"(r2), "=r"(r3) : "r"(addr))

#define MMA16816(d, a, b) \
    asm volatile("mma.sync.aligned.m16n8k16.row.col.f32.f16.f16.f32 " \
                 "{%0,%1,%2,%3}, {%4,%5,%6,%7}, {%8,%9}, {%0,%1,%2,%3};" \
                 : "+f"((d)[0]), "+f"((d)[1]), "+f"((d)[2]), "+f"((d)[3]) \
                 : "r"((a)[0]), "r"((a)[1]), "r"((a)[2]), "r"((a)[3]), \
                   "r"((b)[0]), "r"((b)[1]))

// ---------------------------------------------------------------------------
// Reset kernel: zero flags/cursors each launch (graph-replay safe).
// ---------------------------------------------------------------------------
__global__ void reset_kernel() {
    int tid = threadIdx.x;
    if (tid < MAXG) g_ready[tid] = 0;
    if (tid == 0) { g_cursor = 0; g_done = 0; }
}

// ---------------------------------------------------------------------------
// Work-item decode
// ---------------------------------------------------------------------------
struct Item {
    const __half *Ap, *Bp;
    const float *An, *Bn;
    int t, mi, ni, g;
    float w;
};
__device__ __forceinline__ Item decode_item(int item) {
    Item it;
    int g = item / 10, blk = item % 10;
    it.g = g;
    if (blk < 4) { it.t = 0; it.mi = blk >> 1; it.ni = blk & 1; it.w = 1.0f; }
    else {
        int q = blk - 4;
        it.t = 1 + q / 3;
        int r3 = q % 3;
        it.mi = (r3 == 2) ? 1 : 0;
        it.ni = (r3 == 0) ? 0 : 1;
        it.w = (r3 == 1) ? -1.0f : -0.5f;
    }
    const __half* Ag = (it.t == 2) ? g_yh : g_xh;
    const __half* Bg = (it.t == 0) ? g_yh : ((it.t == 1) ? g_xh : g_yh);
    it.An = ((it.t == 2) ? g_yn : g_xn) + g * NP + it.mi * 128;
    it.Bn = ((it.t == 0) ? g_yn : ((it.t == 1) ? g_xn : g_yn)) + g * NP + it.ni * 128;
    it.Ap = Ag + ((size_t)g * NP + it.mi * 128) * DD;
    it.Bp = Bg + ((size_t)g * NP + it.ni * 128) * DD;
    return it;
}

// ---------------------------------------------------------------------------
// Stage loader: 128x64 fp16 A tile + 128x64 B tile, cp.async, xor-swizzled.
// ---------------------------------------------------------------------------
__device__ __forceinline__ void stage_load(uint32_t sa, const __half* Ap,
                                           const __half* Bp, int tid) {
#pragma unroll
    for (int i = 0; i < 4; i++) {
        int e = tid + i * TPB;
        int r = e >> 3, cc = e & 7;
        uint32_t so = sa + (uint32_t)(r * 128 + ((cc ^ (r & 7)) << 4));
        CP_ASYNC16(so, Ap + (size_t)r * DD + cc * 8);
    }
    uint32_t sb = sa + 16384;
#pragma unroll
    for (int i = 0; i < 4; i++) {
        int e = tid + i * TPB;
        int r = e >> 3, cc = e & 7;
        uint32_t so = sb + (uint32_t)(r * 128 + ((cc ^ (r & 7)) << 4));
        CP_ASYNC16(so, Bp + (size_t)r * DD + cc * 8);
    }
}

// ---------------------------------------------------------------------------
// Fused persistent kernel: producer CTAs do prep (group-major), all CTAs
// then consume GEMM items from an atomic cursor with per-group ready spins.
// Last CTA performs the deterministic final reduction.
// ---------------------------------------------------------------------------
__global__ __launch_bounds__(TPB, 2)
void fused_kernel(const float* __restrict__ x, const float* __restrict__ y,
                  float* __restrict__ out, int G, int nitems) {
    extern __shared__ __align__(16) char dsmem[];   // 2 stages x 32KB
    __shared__ float an_s[128], bn_s[128], red[8];
    __shared__ unsigned int sh_item;
    __shared__ int sh_flag;

    int tid = threadIdx.x, wid = tid >> 5, lane = tid & 31;
    uint32_t s0 = smem_u32(dsmem);

    // ===================== producer phase =====================
    if (blockIdx.x < PREP_CTAS) {
        int wg = blockIdx.x * 8 + wid;
        int nw = PREP_CTAS * 8;
        int total = G * 256;            // per group: 128 x-pairs + 128 y-pairs
        for (int t = wg; t < total; t += nw) {
            int g = t >> 8, r = t & 255;
            int side = r >> 7, pair = r & 127;
            int row0 = g * NP + pair * 2;
            const float4* src = (const float4*)((side ? y : x) + (size_t)row0 * DD);
            __half* hd = (side ? g_yh : g_xh) + (size_t)row0 * DD;

            float4 a0 = src[lane];
            float4 a1 = src[lane + 32];
            float4 b0 = src[64 + lane];
            float4 b1 = src[64 + lane + 32];

            float sa = 0.f, sb = 0.f;
            uint2 pk; __half2 h01, h23;
            h01 = __floats2half2_rn(a0.x, a0.y); h23 = __floats2half2_rn(a0.z, a0.w);
            pk.x = *(uint32_t*)&h01; pk.y = *(uint32_t*)&h23;
            ((uint2*)hd)[lane] = pk;
            sa += a0.x * a0.x + a0.y * a0.y + a0.z * a0.z + a0.w * a0.w;
            h01 = __floats2half2_rn(a1.x, a1.y); h23 = __floats2half2_rn(a1.z, a1.w);
            pk.x = *(uint32_t*)&h01; pk.y = *(uint32_t*)&h23;
            ((uint2*)hd)[lane + 32] = pk;
            sa += a1.x * a1.x + a1.y * a1.y + a1.z * a1.z + a1.w * a1.w;
            h01 = __floats2half2_rn(b0.x, b0.y); h23 = __floats2half2_rn(b0.z, b0.w);
            pk.x = *(uint32_t*)&h01; pk.y = *(uint32_t*)&h23;
            ((uint2*)hd)[64 + lane] = pk;
            sb += b0.x * b0.x + b0.y * b0.y + b0.z * b0.z + b0.w * b0.w;
            h01 = __floats2half2_rn(b1.x, b1.y); h23 = __floats2half2_rn(b1.z, b1.w);
            pk.x = *(uint32_t*)&h01; pk.y = *(uint32_t*)&h23;
            ((uint2*)hd)[64 + lane + 32] = pk;
            sb += b1.x * b1.x + b1.y * b1.y + b1.z * b1.z + b1.w * b1.w;

#pragma unroll
            for (int o = 16; o; o >>= 1) {
                sa += __shfl_xor_sync(0xffffffffu, sa, o);
                sb += __shfl_xor_sync(0xffffffffu, sb, o);
            }
            if (lane == 0) {
                float* dst = side ? g_yn : g_xn;
                dst[row0] = sa;
                dst[row0 + 1] = sb;
            }
            __syncwarp();
            if (lane == 0) {
                __threadfence();                         // release all lanes' stores
                atomicAdd(&g_ready[g], 1u);              // REDG, no return
            }
        }
    }

    // ===================== consumer phase =====================
    if (tid == 0) sh_item = atomicAdd(&g_cursor, 1u);
    __syncthreads();
    unsigned int item = sh_item;

    if (item < (unsigned)nitems) {
        Item cur = decode_item((int)item);

        // wait for first item's group, then prime the pipeline
        if (tid == 0) {
            while (ld_acq(&g_ready[cur.g]) < 256u) __nanosleep(100);
        }
        __syncthreads();
        stage_load(s0, cur.Ap, cur.Bp, tid);
        CP_COMMIT();

        while (true) {
            if (tid == 0) sh_item = atomicAdd(&g_cursor, 1u);

            if (tid < 128) an_s[tid] = cur.An[tid];
            else           bn_s[tid - 128] = cur.Bn[tid - 128];

            float acc[4][4][4];
#pragma unroll
            for (int a = 0; a < 4; a++)
#pragma unroll
                for (int b = 0; b < 4; b++)
#pragma unroll
                    for (int c = 0; c < 4; c++) acc[a][b][c] = 0.f;

            unsigned int nxt = 0;
            bool has_next = false, prefetched = false;
            Item nx;

            for (int kb = 0; kb < 4; kb++) {              // 4 x KT=64
                CP_WAIT0();
                __syncthreads();
                if (kb == 0) {
                    nxt = sh_item;                        // visible via barrier
                    has_next = nxt < (unsigned)nitems;
                    if (has_next) nx = decode_item((int)nxt);
                }
                if (kb == 2 && tid == 0)                  // non-blocking peek
                    sh_flag = has_next && (ld_acq(&g_ready[nx.g]) >= 256u);
                if (kb < 3) {
                    stage_load(s0 + ((kb + 1) & 1) * 32768,
                               cur.Ap + (kb + 1) * 64, cur.Bp + (kb + 1) * 64, tid);
                    CP_COMMIT();
                } else if (has_next && sh_flag) {         // cross-item prefetch
                    prefetched = true;
                    stage_load(s0, nx.Ap, nx.Bp, tid);
                    CP_COMMIT();
                }
                uint32_t ab = s0 + (kb & 1) * 32768;
                uint32_t bb = ab + 16384;

#pragma unroll
                for (int ks = 0; ks < 4; ks++) {          // 4 x k16 per stage
                    int k0 = ks * 16;
                    uint32_t af[4][4], bf[4][2];
                    {
                        int arow = wm_of(wid) + (lane & 15);
                        int accc = (k0 >> 3) + (lane >> 4);
#pragma unroll
                        for (int mt = 0; mt < 4; mt++) {
                            int row = arow + mt * 16;
                            uint32_t ad = ab + (uint32_t)(row * 128 + ((accc ^ (row & 7)) << 4));
                            LDSM_X4(af[mt][0], af[mt][1], af[mt][2], af[mt][3], ad);
                        }
                    }
                    {
                        int brow0 = wn_of(wid) + (lane & 7) + ((lane >> 4) << 3);
                        int bcc = (k0 >> 3) + ((lane >> 3) & 1);
#pragma unroll
                        for (int p = 0; p < 2; p++) {
                            int row = brow0 + p * 16;
                            uint32_t bd = bb + (uint32_t)(row * 128 + ((bcc ^ (row & 7)) << 4));
                            uint32_t q0, q1, q2, q3;
                            LDSM_X4(q0, q1, q2, q3, bd);
                            bf[2 * p][0] = q0; bf[2 * p][1] = q1;
                            bf[2 * p + 1][0] = q2; bf[2 * p + 1][1] = q3;
                        }
                    }
#pragma unroll
                    for (int mt = 0; mt < 4; mt++)
#pragma unroll
                        for (int nt = 0; nt < 4; nt++)
                            MMA16816(acc[mt][nt], af[mt], bf[nt]);
                }
            }

            // ---- epilogue
            bool diagblk = (cur.t != 0) && (cur.mi == cur.ni);
            float sum = 0.f;
#pragma unroll
            for (int mt = 0; mt < 4; mt++) {
                int i0 = wm_of(wid) + mt * 16 + (lane >> 2);
                float an0 = an_s[i0], an1 = an_s[i0 + 8];
#pragma unroll
                for (int nt = 0; nt < 4; nt++) {
                    int j0 = wn_of(wid) + nt * 8 + 2 * (lane & 3);
                    float bn0 = bn_s[j0], bn1 = bn_s[j0 + 1];
                    float* c = acc[mt][nt];
                    float d00 = an0 + bn0 - 2.0f * c[0];
                    float d01 = an0 + bn1 - 2.0f * c[1];
                    float d10 = an1 + bn0 - 2.0f * c[2];
                    float d11 = an1 + bn1 - 2.0f * c[3];
                    float s00 = sqrtf(fmaxf(d00, 0.f));
                    float s01 = sqrtf(fmaxf(d01, 0.f));
                    float s10 = sqrtf(fmaxf(d10, 0.f));
                    float s11 = sqrtf(fmaxf(d11, 0.f));
                    if (diagblk) {
                        if (i0 == j0)         s00 = 0.f;
                        if (i0 == j0 + 1)     s01 = 0.f;
                        if (i0 + 8 == j0)     s10 = 0.f;
                        if (i0 + 8 == j0 + 1) s11 = 0.f;
                    }
                    sum += s00 + s01 + s10 + s11;
                }
            }
#pragma unroll
            for (int o = 16; o; o >>= 1) sum += __shfl_xor_sync(0xffffffffu, sum, o);
            if (lane == 0) red[wid] = sum;
            __syncthreads();
            if (wid == 0) {
                float v = (lane < 8) ? red[lane] : 0.f;
#pragma unroll
                for (int o = 4; o; o >>= 1) v += __shfl_xor_sync(0xffffffffu, v, o);
                if (lane == 0) g_part[item] = cur.w * v;
            }
            __syncthreads();

            if (!has_next) break;
            item = nxt;
            cur = nx;
            if (!prefetched) {
                if (tid == 0) {
                    while (ld_acq(&g_ready[cur.g]) < 256u) __nanosleep(100);
                }
                __syncthreads();
                stage_load(s0, cur.Ap, cur.Bp, tid);
                CP_COMMIT();
            }
        }
    }

    // ===================== final reduction (last CTA) =====================
    if (tid == 0) {
        __threadfence();
        unsigned int old = atomicAdd(&g_done, 1u);
        sh_flag = (old == gridDim.x - 1);
    }
    __syncthreads();
    if (sh_flag) {
        __threadfence();   // acquire all g_part writes
        float s = 0.f;
        for (int i = tid; i < nitems; i += TPB) s += g_part[i];
#pragma unroll
        for (int o = 16; o; o >>= 1) s += __shfl_xor_sync(0xffffffffu, s, o);
        if (lane == 0) red[wid] = s;
        __syncthreads();
        if (wid == 0) {
            float v = (lane < 8) ? red[lane] : 0.f;
#pragma unroll
            for (int o = 4; o; o >>= 1) v += __shfl_xor_sync(0xffffffffu, v, o);
            if (lane == 0) out[0] = v / ((float)NP * (float)NP * (float)G);
        }
    }
}

// ---------------------------------------------------------------------------
extern "C" void kernel_launch(void* const* d_in, const int* in_sizes, int n_in,
                              void* d_out, int out_size) {
    const float* x = (const float*)d_in[0];
    const float* y = (const float*)d_in[1];
    int G = in_sizes[0] / (NP * DD);
    if (G > MAXG) G = MAXG;
    int nitems = 10 * G;

    static int smem_set = 0;
    if (!smem_set) {
        cudaFuncSetAttribute(fused_kernel,
                             cudaFuncAttributeMaxDynamicSharedMemorySize, 65536);
        smem_set = 1;
    }

    reset_kernel<<<1, 256>>>();
    fused_kernel<<<GRID_CTAS, TPB, 65536>>>(x, y, (float*)d_out, G, nitems);
}